// round 16
// baseline (speedup 1.0000x reference)
#include <cuda_runtime.h>
#include <math.h>
#include <stdint.h>

#define SQ   2048
#define NB   4
#define EE   1024
#define FF   4096
#define NEXP 8
#define CAPN 2048
#define NH   16
#define HD   64
#define TOK  (SQ*NB)

// ---------------- pre-split global planes ----------------
__device__ float g_qnh[TOK*EE]; __device__ float g_qnl[TOK*EE];
__device__ float g_knh[TOK*EE]; __device__ float g_knl[TOK*EE];
__device__ float g_vnh[TOK*EE]; __device__ float g_vnl[TOK*EE];
__device__ float g_qph[TOK*EE]; __device__ float g_qpl[TOK*EE];
__device__ float g_kph[TOK*EE]; __device__ float g_kpl[TOK*EE];
__device__ float g_vph[TOK*EE]; __device__ float g_vpl[TOK*EE];
__device__ float g_ctxh[TOK*EE]; __device__ float g_ctxl[TOK*EE];
__device__ float g_x[TOK*EE];
__device__ float g_xn[TOK*EE];
__device__ float g_iwh[3*EE*EE]; __device__ float g_iwl[3*EE*EE];
__device__ float g_owh[EE*EE];   __device__ float g_owl[EE*EE];
__device__ float g_h[(size_t)NEXP*CAPN*FF];
__device__ float g_ropeinv[EE/2];
__device__ int   g_eid[TOK];
__device__ int   g_list[NEXP*CAPN];
__device__ int   g_cnt[NEXP];

// ---------------- helpers ----------------
__device__ __forceinline__ float tf32_rna(float x) {
    uint32_t u; asm("cvt.rna.tf32.f32 %0, %1;" : "=r"(u) : "f"(x));
    return __uint_as_float(u);
}
__device__ __forceinline__ void split2(float x, float& h, float& l) {
    h = tf32_rna(x); l = tf32_rna(x - h);
}
__device__ __forceinline__ void mma8(float* d, const float* a, const float* b) {
    asm volatile(
        "mma.sync.aligned.m16n8k8.row.col.f32.tf32.tf32.f32 "
        "{%0,%1,%2,%3}, {%4,%5,%6,%7}, {%8,%9}, {%0,%1,%2,%3};"
        : "+f"(d[0]), "+f"(d[1]), "+f"(d[2]), "+f"(d[3])
        : "r"(__float_as_uint(a[0])), "r"(__float_as_uint(a[1])),
          "r"(__float_as_uint(a[2])), "r"(__float_as_uint(a[3])),
          "r"(__float_as_uint(b[0])), "r"(__float_as_uint(b[1])));
}
__device__ __forceinline__ void cpa16(uint32_t dst, const void* src) {
    asm volatile("cp.async.cg.shared.global [%0], [%1], 16;" :: "r"(dst), "l"(src));
}
__device__ __forceinline__ void cp_commit() { asm volatile("cp.async.commit_group;"); }
template<int N> __device__ __forceinline__ void cp_wait() {
    asm volatile("cp.async.wait_group %0;" :: "n"(N));
}
__device__ __forceinline__ uint32_t s2u(const void* p) {
    uint32_t a;
    asm("{ .reg .u64 t; cvta.to.shared.u64 t, %1; cvt.u32.u64 %0, t; }" : "=r"(a) : "l"(p));
    return a;
}

__device__ __forceinline__ float blk_sum256(float v) {
    __shared__ float red[8];
    #pragma unroll
    for (int o = 16; o > 0; o >>= 1) v += __shfl_xor_sync(0xffffffffu, v, o);
    if ((threadIdx.x & 31) == 0) red[threadIdx.x >> 5] = v;
    __syncthreads();
    float s = 0.f;
    #pragma unroll
    for (int i = 0; i < 8; i++) s += red[i];
    __syncthreads();
    return s;
}

// ---------------- one-shot weight split (+ rope table) ----------------
__global__ void split_w_kernel(const float* __restrict__ inw, const float* __restrict__ outw) {
    int i = blockIdx.x * 256 + threadIdx.x;
    if (i < EE / 2)
        g_ropeinv[i] = (float)(1.0 / pow(10000.0, (double)i * (1.0 / 512.0)));
    const int NIW = 3 * EE * EE;
    float h, l;
    if (i < NIW) {
        split2(inw[i], h, l);
        g_iwh[i] = h; g_iwl[i] = l;
    } else {
        int j = i - NIW;
        split2(outw[j], h, l);
        g_owh[j] = h; g_owl[j] = l;
    }
}

// ---------------- LN1 + RoPE ----------------
__global__ void ln1_rope_kernel(const float* __restrict__ q, const float* __restrict__ k,
                                const float* __restrict__ v,
                                const float* __restrict__ sc, const float* __restrict__ bi) {
    int z = blockIdx.y, t = blockIdx.x;
    const float* x = ((z == 0) ? q : (z == 1) ? k : v) + (size_t)t * EE;
    float* oh = ((z == 0) ? g_qnh : (z == 1) ? g_knh : g_vnh) + (size_t)t * EE;
    float* ol = ((z == 0) ? g_qnl : (z == 1) ? g_knl : g_vnl) + (size_t)t * EE;
    int srow = t / NB;
    float s = 0.f;
    for (int i = threadIdx.x; i < EE; i += 256) s += x[i];
    float mean = blk_sum256(s) * (1.0f / EE);
    float vs = 0.f;
    for (int i = threadIdx.x; i < EE; i += 256) { float d = x[i] - mean; vs += d * d; }
    float rstd = rsqrtf(blk_sum256(vs) * (1.0f / EE) + 1e-5f);
    for (int i = threadIdx.x; i < EE / 2; i += 256) {
        float x1 = (x[i]       - mean) * rstd * sc[i]       + bi[i];
        float x2 = (x[i + 512] - mean) * rstd * sc[i + 512] + bi[i + 512];
        float fr = (float)srow * g_ropeinv[i];
        float sn, cs; sincosf(fr, &sn, &cs);
        float o1 = x1 * cs - x2 * sn;
        float o2 = x1 * sn + x2 * cs;
        float h, l;
        split2(o1, h, l); oh[i] = h;       ol[i] = l;
        split2(o2, h, l); oh[i + 512] = h; ol[i + 512] = l;
    }
}

// ---------------- LN2 + router fused ----------------
__global__ void ln2_router_kernel(const float* __restrict__ sc, const float* __restrict__ bi,
                                  const float* __restrict__ rw) {
    int t = blockIdx.x;
    const float* x = g_x + (size_t)t * EE;
    float* o = g_xn + (size_t)t * EE;
    float s = 0.f;
    for (int i = threadIdx.x; i < EE; i += 256) s += x[i];
    float mean = blk_sum256(s) * (1.0f / EE);
    float vs = 0.f;
    for (int i = threadIdx.x; i < EE; i += 256) { float d = x[i] - mean; vs += d * d; }
    float rstd = rsqrtf(blk_sum256(vs) * (1.0f / EE) + 1e-5f);
    float a[NEXP];
    #pragma unroll
    for (int e = 0; e < NEXP; e++) a[e] = 0.f;
    for (int i = threadIdx.x; i < EE; i += 256) {
        float xn = (x[i] - mean) * rstd * sc[i] + bi[i];
        o[i] = tf32_rna(xn);
        #pragma unroll
        for (int e = 0; e < NEXP; e++) a[e] += xn * rw[i * NEXP + e];
    }
    __shared__ float red[8][NEXP];
    #pragma unroll
    for (int e = 0; e < NEXP; e++) {
        float v = a[e];
        #pragma unroll
        for (int o2 = 16; o2 > 0; o2 >>= 1) v += __shfl_xor_sync(0xffffffffu, v, o2);
        if ((threadIdx.x & 31) == 0) red[threadIdx.x >> 5][e] = v;
    }
    __syncthreads();
    if (threadIdx.x == 0) {
        int best = 0; float bv = -1e30f;
        #pragma unroll
        for (int e = 0; e < NEXP; e++) {
            float sum = 0.f;
            #pragma unroll
            for (int w = 0; w < 8; w++) sum += red[w][e];
            if (sum > bv) { bv = sum; best = e; }
        }
        g_eid[t] = best;
    }
}

// ================= 3xTF32 GEMM, 256x128 tile, 512 threads, single-barrier 2-stage =================
// warp grid: 8 M x 2 N; warp tile 32x64. Stage: Ah(256x20) Al Bh(128x20) Bl = 15360 floats.
#define BIG_AH 0
#define BIG_AL 5120
#define BIG_BH 10240
#define BIG_BL 12800
#define BIG_STAGE 15360
#define SMBIG_BYTES (2 * BIG_STAGE * 4)   // 122880

__device__ __forceinline__ void gemm_tc_big(
    const float* __restrict__ Ahg, const float* __restrict__ Alg,
    const float* __restrict__ Bhg, const float* __restrict__ Blg,
    int lda, int ldb, int K, int row0, int col0, int valid,
    float acc[2][8][4])
{
    extern __shared__ float smf[];
    const int tid = threadIdx.x;
    const int warp = tid >> 5, lane = tid & 31;
    const int g = lane >> 2, tq = lane & 3;
    const int wm = (warp & 7) * 32, wn = (warp >> 3) * 64;

    uint32_t smb = s2u(smf);

    // A: 1024 chunks (256 rows x 4), 2 per thread; B: 512 chunks, 1 per thread
    const float* pAh[2]; const float* pAl[2];
    uint32_t dstA[2];
    #pragma unroll
    for (int i = 0; i < 2; i++) {
        int id = tid + i * 512;
        int r = id >> 2, q = (id & 3) * 4;
        int gr = row0 + r; if (gr >= valid) gr = valid - 1;
        pAh[i] = Ahg + (size_t)gr * lda + q;
        pAl[i] = Alg + (size_t)gr * lda + q;
        dstA[i] = BIG_AH + r * 20 + q;
    }
    const float* pBh; const float* pBl;
    uint32_t dstB;
    {
        int r = tid >> 2, q = (tid & 3) * 4;
        pBh = Bhg + (size_t)(col0 + r) * ldb + q;
        pBl = Blg + (size_t)(col0 + r) * ldb + q;
        dstB = BIG_BH + r * 20 + q;
    }

    auto docopy = [&](int k0, int st) {
        uint32_t base = smb + (uint32_t)(st * BIG_STAGE) * 4u;
        #pragma unroll
        for (int i = 0; i < 2; i++) {
            cpa16(base + dstA[i] * 4, pAh[i] + k0);
            cpa16(base + (dstA[i] + (BIG_AL - BIG_AH)) * 4, pAl[i] + k0);
        }
        cpa16(base + dstB * 4, pBh + k0);
        cpa16(base + (dstB + (BIG_BL - BIG_BH)) * 4, pBl + k0);
    };

    auto mmaT = [&](int st) {
        const float* Ah = smf + st * BIG_STAGE + BIG_AH;
        const float* Al = smf + st * BIG_STAGE + BIG_AL;
        const float* Bh = smf + st * BIG_STAGE + BIG_BH;
        const float* Bl = smf + st * BIG_STAGE + BIG_BL;
        #pragma unroll
        for (int ks = 0; ks < 2; ks++) {
            int kk = ks * 8 + tq;
            float ah[2][4], al[2][4];
            #pragma unroll
            for (int mt = 0; mt < 2; mt++) {
                int r = wm + mt * 16 + g;
                ah[mt][0] = Ah[r * 20 + kk];       ah[mt][1] = Ah[(r + 8) * 20 + kk];
                ah[mt][2] = Ah[r * 20 + kk + 4];   ah[mt][3] = Ah[(r + 8) * 20 + kk + 4];
                al[mt][0] = Al[r * 20 + kk];       al[mt][1] = Al[(r + 8) * 20 + kk];
                al[mt][2] = Al[r * 20 + kk + 4];   al[mt][3] = Al[(r + 8) * 20 + kk + 4];
            }
            #pragma unroll
            for (int nt = 0; nt < 8; nt++) {
                int n = wn + nt * 8 + g;
                float bh[2] = { Bh[n * 20 + kk], Bh[n * 20 + kk + 4] };
                float bl[2] = { Bl[n * 20 + kk], Bl[n * 20 + kk + 4] };
                #pragma unroll
                for (int mt = 0; mt < 2; mt++) {
                    mma8(acc[mt][nt], ah[mt], bl);
                    mma8(acc[mt][nt], al[mt], bh);
                    mma8(acc[mt][nt], ah[mt], bh);
                }
            }
        }
    };

    docopy(0, 0); cp_commit();
    cp_wait<0>(); __syncthreads();
    int st = 0;
    for (int k0 = 0; k0 < K; k0 += 16) {
        if (k0 + 16 < K) { docopy(k0 + 16, st ^ 1); cp_commit(); }
        mmaT(st);
        cp_wait<0>(); __syncthreads();
        st ^= 1;
    }
}

// ================= 1xTF32 GEMM, k-tile 32, 3-stage pipeline (MoE) =================
#define KA_STR 36
#define K32_STAGE (128 * KA_STR + 32 * 132)
#define SMK32_BYTES (3 * K32_STAGE * 4)

__device__ __forceinline__ void gemm_tc_1xk32(
    const float* __restrict__ Ag, const float* __restrict__ Bg,
    int lda, int ldb, int K, int row0, int col0,
    const int* __restrict__ gather, int valid,
    float acc[2][8][4])
{
    extern __shared__ float smf[];
    const int tid = threadIdx.x;
    const int warp = tid >> 5, lane = tid & 31;
    const int g = lane >> 2, tq = lane & 3;
    const int wm = (warp & 3) * 32, wn = (warp >> 2) * 64;

    uint32_t smb = s2u(smf);

    const float* pA[4]; const float* pB[4];
    uint32_t dA[4], dB[4];
    #pragma unroll
    for (int i = 0; i < 4; i++) {
        int id = tid + i * 256;
        int r = id >> 3, q = (id & 7) * 4;
        int gr = row0 + r; if (gr >= valid) gr = valid - 1;
        int ar = gather ? gather[gr] : gr;
        pA[i] = Ag + (size_t)ar * lda + q;
        dA[i] = r * KA_STR + q;
        int kr = id >> 5, n4 = (id & 31) * 4;
        pB[i] = Bg + (size_t)kr * ldb + col0 + n4;
        dB[i] = 128 * KA_STR + kr * 132 + n4;
    }

    auto docopy = [&](int k0, int st) {
        uint32_t base = smb + (uint32_t)(st * K32_STAGE) * 4u;
        #pragma unroll
        for (int i = 0; i < 4; i++) cpa16(base + dA[i] * 4, pA[i] + k0);
        #pragma unroll
        for (int i = 0; i < 4; i++) cpa16(base + dB[i] * 4, pB[i] + (size_t)k0 * ldb);
    };

    auto mmaT = [&](int st) {
        const float* As = smf + st * K32_STAGE;
        const float* Bs = As + 128 * KA_STR;
        #pragma unroll
        for (int ks = 0; ks < 4; ks++) {
            int kk = ks * 8 + tq;
            float ah[2][4];
            #pragma unroll
            for (int mt = 0; mt < 2; mt++) {
                int r = wm + mt * 16 + g;
                ah[mt][0] = As[r * KA_STR + kk];     ah[mt][1] = As[(r + 8) * KA_STR + kk];
                ah[mt][2] = As[r * KA_STR + kk + 4]; ah[mt][3] = As[(r + 8) * KA_STR + kk + 4];
            }
            #pragma unroll
            for (int nt = 0; nt < 8; nt++) {
                int n = wn + nt * 8 + g;
                float bh[2] = { Bs[kk * 132 + n], Bs[(kk + 4) * 132 + n] };
                #pragma unroll
                for (int mt = 0; mt < 2; mt++)
                    mma8(acc[mt][nt], ah[mt], bh);
            }
        }
    };

    const int T = K >> 5;
    docopy(0, 0); cp_commit();
    docopy(32, 1); cp_commit();
    int s0 = 0;
    for (int t = 0; t < T; t++) {
        if (t + 1 < T) cp_wait<1>(); else cp_wait<0>();
        __syncthreads();
        if (t + 2 < T) {
            int s2 = s0 + 2; if (s2 >= 3) s2 -= 3;
            docopy((t + 2) * 32, s2);
            cp_commit();
        }
        mmaT(s0);
        if (++s0 == 3) s0 = 0;
    }
    __syncthreads();
}

#define ZERO_ACC(acc) { \
    _Pragma("unroll") for (int a_ = 0; a_ < 2; a_++) \
    _Pragma("unroll") for (int b_ = 0; b_ < 8; b_++) \
    _Pragma("unroll") for (int c_ = 0; c_ < 4; c_++) acc[a_][b_][c_] = 0.f; }

// ---------------- QKV projection (3xTF32, big tile); permuted epilogue layouts ----------------
__global__ __launch_bounds__(512, 1) void qkv_tc_kernel(const float* __restrict__ bias) {
    int z = blockIdx.z;
    const float* Ah = (z == 0) ? g_qnh : (z == 1) ? g_knh : g_vnh;
    const float* Al = (z == 0) ? g_qnl : (z == 1) ? g_knl : g_vnl;
    float* Ch = (z == 0) ? g_qph : (z == 1) ? g_kph : g_vph;
    float* Cl = (z == 0) ? g_qpl : (z == 1) ? g_kpl : g_vpl;
    int row0 = blockIdx.y * 256, col0 = blockIdx.x * 128;
    float acc[2][8][4]; ZERO_ACC(acc);
    gemm_tc_big(Ah, Al, g_iwh + (size_t)z * EE * EE, g_iwl + (size_t)z * EE * EE,
                EE, EE, EE, row0, col0, TOK, acc);
    int warp = threadIdx.x >> 5, lane = threadIdx.x & 31;
    int wm = (warp & 7) * 32, wn = (warp >> 3) * 64;
    int g = lane >> 2, tq = lane & 3;
    float scale = (z == 0) ? 0.125f : 1.0f;
    int pi0 = ((tq & 1) << 2) | (tq >> 1);
    #pragma unroll
    for (int mt = 0; mt < 2; mt++) {
        #pragma unroll
        for (int p = 0; p < 2; p++) {
            int r = row0 + wm + mt * 16 + g + p * 8;
            #pragma unroll
            for (int nt = 0; nt < 8; nt++) {
                int c = col0 + wn + nt * 8 + tq * 2;
                float v0 = (acc[mt][nt][p * 2]     + bias[z * EE + c])     * scale;
                float v1 = (acc[mt][nt][p * 2 + 1] + bias[z * EE + c + 1]) * scale;
                float h0, l0, h1, l1;
                split2(v0, h0, l0); split2(v1, h1, l1);
                if (z < 2) {
                    size_t base = (size_t)r * EE + (c & ~7);
                    Ch[base + pi0]     = h0;  Ch[base + pi0 + 2] = h1;
                    Cl[base + pi0]     = l0;  Cl[base + pi0 + 2] = l1;
                } else {
                    int kt = r >> 2, bb = r & 3;
                    size_t vb = (((size_t)(kt >> 1) * NB + bb) * EE + c) * 2 + (kt & 1);
                    Ch[vb]     = h0;  Ch[vb + 2] = h1;
                    Cl[vb]     = l0;  Cl[vb + 2] = l1;
                }
            }
        }
    }
}

// ---------------- out projection (3xTF32, big tile) + bias + residual ----------------
__global__ __launch_bounds__(512, 1) void outproj_tc_kernel(const float* __restrict__ bias,
                                                            const float* __restrict__ resid,
                                                            float* __restrict__ out) {
    int row0 = blockIdx.y * 256, col0 = blockIdx.x * 128;
    float acc[2][8][4]; ZERO_ACC(acc);
    gemm_tc_big(g_ctxh, g_ctxl, g_owh, g_owl, EE, EE, EE, row0, col0, TOK, acc);
    int warp = threadIdx.x >> 5, lane = threadIdx.x & 31;
    int wm = (warp & 7) * 32, wn = (warp >> 3) * 64;
    int g = lane >> 2, tq = lane & 3;
    #pragma unroll
    for (int mt = 0; mt < 2; mt++) {
        #pragma unroll
        for (int p = 0; p < 2; p++) {
            int r = row0 + wm + mt * 16 + g + p * 8;
            #pragma unroll
            for (int nt = 0; nt < 8; nt++) {
                int c = col0 + wn + nt * 8 + tq * 2;
                size_t o = (size_t)r * EE + c;
                float v0 = acc[mt][nt][p * 2]     + bias[c]     + resid[o];
                float v1 = acc[mt][nt][p * 2 + 1] + bias[c + 1] + resid[o + 1];
                g_x[o] = v0; g_x[o + 1] = v1;
                out[o] = v0; out[o + 1] = v1;
            }
        }
    }
}

// ================= flash attention (R15: no-max softmax, single-barrier) =================
#define QS  76
#define KSS 72
#define VPS 136
#define QH_O 0
#define QL_O (128*QS)
#define KH_O (2*128*QS)
#define KL_O (KH_O + 2*64*KSS)
#define VH_O (KL_O + 2*64*KSS)
#define VL_O (VH_O + 2*32*VPS)
#define ATTN_SMEM_BYTES ((VL_O + 2*32*VPS) * 4)

__global__ __launch_bounds__(256, 1) void attn_tc_kernel() {
    extern __shared__ float sm[];
    uint32_t smb = s2u(sm);

    int bh = blockIdx.y;
    int b = bh >> 4, h = bh & 15;
    int q0 = blockIdx.x * 128;
    int tid = threadIdx.x, warp = tid >> 5, lane = tid & 31;
    int g = lane >> 2, tq = lane & 3;
    int qw = warp * 16;

    const int row = tid >> 2, ch = (tid & 3) * 16;
    const int vp = tid >> 3, vch = (tid & 7) * 16;

    {
        size_t s0 = ((size_t)(q0 + row) * NB + b) * EE + h * HD + ch;
        size_t s1 = ((size_t)(q0 + row + 64) * NB + b) * EE + h * HD + ch;
        #pragma unroll
        for (int j = 0; j < 4; j++) {
            int c4 = ch + j * 4;
            cpa16(smb + (QH_O + row * QS + c4) * 4,        g_qph + s0 + j * 4);
            cpa16(smb + (QL_O + row * QS + c4) * 4,        g_qpl + s0 + j * 4);
            cpa16(smb + (QH_O + (row + 64) * QS + c4) * 4, g_qph + s1 + j * 4);
            cpa16(smb + (QL_O + (row + 64) * QS + c4) * 4, g_qpl + s1 + j * 4);
        }
    }

    auto docopy = [&](int n0, int st) {
        size_t ksrc = ((size_t)(n0 + row) * NB + b) * EE + h * HD + ch;
        uint32_t kd = (uint32_t)(KH_O + st * 64 * KSS + row * KSS + ch);
        #pragma unroll
        for (int j = 0; j < 4; j++) {
            uint32_t f = j * 4;
            cpa16(smb + (kd + f) * 4,                 g_kph + ksrc + f);
            cpa16(smb + (kd + (KL_O - KH_O) + f) * 4, g_kpl + ksrc + f);
        }
        size_t vsrc = (((size_t)((n0 >> 1) + vp) * NB + b) * EE + h * HD) * 2 + vch;
        uint32_t vd = (uint32_t)(VH_O + st * 32 * VPS + vp * VPS + vch);
        #pragma unroll
        for (int j = 0; j < 4; j++) {
            uint32_t f = j * 4;
            cpa16(smb + (vd + f) * 4,                 g_vph + vsrc + f);
            cpa16(smb + (vd + (VL_O - VH_O) + f) * 4, g_vpl + vsrc + f);
        }
    };

    docopy(0, 0); cp_commit();
    cp_wait<0>(); __syncthreads();

    float qh[8][4], ql[8][4];
    {
        const float* Qh = sm + QH_O;
        const float* Ql = sm + QL_O;
        int r = qw + g;
        #pragma unroll
        for (int ks = 0; ks < 8; ks++) {
            int off = ks * 8 + tq * 2;
            float2 a0 = *(const float2*)&Qh[r * QS + off];
            float2 a1 = *(const float2*)&Qh[(r + 8) * QS + off];
            qh[ks][0] = a0.x; qh[ks][1] = a1.x; qh[ks][2] = a0.y; qh[ks][3] = a1.y;
            float2 b0 = *(const float2*)&Ql[r * QS + off];
            float2 b1 = *(const float2*)&Ql[(r + 8) * QS + off];
            ql[ks][0] = b0.x; ql[ks][1] = b1.x; ql[ks][2] = b0.y; ql[ks][3] = b1.y;
        }
    }

    float o[8][4];
    #pragma unroll
    for (int nt = 0; nt < 8; nt++)
        #pragma unroll
        for (int j = 0; j < 4; j++) o[nt][j] = 0.f;
    float lsum0 = 0.f, lsum1 = 0.f;

    int st = 0;
    for (int n0 = 0; n0 < SQ; n0 += 64) {
        if (n0 + 64 < SQ) { docopy(n0 + 64, st ^ 1); cp_commit(); }

        const float* Kh = sm + KH_O + st * 64 * KSS;
        const float* Kl = sm + KL_O + st * 64 * KSS;
        const float* Vh = sm + VH_O + st * 32 * VPS;
        const float* Vl = sm + VL_O + st * 32 * VPS;

        float s[8][4];
        #pragma unroll
        for (int nt = 0; nt < 8; nt++)
            #pragma unroll
            for (int j = 0; j < 4; j++) s[nt][j] = 0.f;
        #pragma unroll
        for (int ks = 0; ks < 8; ks++) {
            int off = ks * 8 + tq * 2;
            #pragma unroll
            for (int nt = 0; nt < 8; nt++) {
                int n = nt * 8 + g;
                float2 bh2 = *(const float2*)&Kh[n * KSS + off];
                float2 bl2 = *(const float2*)&Kl[n * KSS + off];
                float bhv[2] = { bh2.x, bh2.y };
                float blv[2] = { bl2.x, bl2.y };
                mma8(s[nt], qh[ks], blv);
                mma8(s[nt], ql[ks], bhv);
                mma8(s[nt], qh[ks], bhv);
            }
        }

        #pragma unroll
        for (int nt = 0; nt < 8; nt++) {
            s[nt][0] = __expf(s[nt][0]); lsum0 += s[nt][0];
            s[nt][1] = __expf(s[nt][1]); lsum0 += s[nt][1];
            s[nt][2] = __expf(s[nt][2]); lsum1 += s[nt][2];
            s[nt][3] = __expf(s[nt][3]); lsum1 += s[nt][3];
        }

        #pragma unroll
        for (int ks = 0; ks < 8; ks++) {
            float ah[4], al[4];
            split2(s[ks][0], ah[0], al[0]);
            split2(s[ks][2], ah[1], al[1]);
            split2(s[ks][1], ah[2], al[2]);
            split2(s[ks][3], ah[3], al[3]);
            int vrow = ks * 4 + tq;
            #pragma unroll
            for (int nt = 0; nt < 8; nt++) {
                int n = nt * 8 + g;
                float2 bh2 = *(const float2*)&Vh[vrow * VPS + n * 2];
                float2 bl2 = *(const float2*)&Vl[vrow * VPS + n * 2];
                float bhv[2] = { bh2.x, bh2.y };
                float blv[2] = { bl2.x, bl2.y };
                mma8(o[nt], ah, blv);
                mma8(o[nt], al, bhv);
                mma8(o[nt], ah, bhv);
            }
        }

        cp_wait<0>(); __syncthreads();
        st ^= 1;
    }

    lsum0 += __shfl_xor_sync(0xffffffffu, lsum0, 1);
    lsum0 += __shfl_xor_sync(0xffffffffu, lsum0, 2);
    lsum1 += __shfl_xor_sync(0xffffffffu, lsum1, 1);
    lsum1 += __shfl_xor_sync(0xffffffffu, lsum1, 2);
    float inv0 = 1.0f / lsum0, inv1 = 1.0f / lsum1;

    int r0 = q0 + qw + g, r1 = r0 + 8;
    #pragma unroll
    for (int nt = 0; nt < 8; nt++) {
        int d = nt * 8 + tq * 2;
        size_t o0 = ((size_t)r0 * NB + b) * EE + h * HD + d;
        size_t o1 = ((size_t)r1 * NB + b) * EE + h * HD + d;
        float h0, l0v, h1, l1v;
        split2(o[nt][0] * inv0, h0, l0v); split2(o[nt][1] * inv0, h1, l1v);
        *(float2*)&g_ctxh[o0] = make_float2(h0, h1);
        *(float2*)&g_ctxl[o0] = make_float2(l0v, l1v);
        split2(o[nt][2] * inv1, h0, l0v); split2(o[nt][3] * inv1, h1, l1v);
        *(float2*)&g_ctxh[o1] = make_float2(h0, h1);
        *(float2*)&g_ctxl[o1] = make_float2(l0v, l1v);
    }
}

// ---------------- capacity: warp-ballot scan ----------------
__global__ void capacity_kernel() {
    int warp = threadIdx.x >> 5, lane = threadIdx.x & 31;
    if (warp >= NEXP) return;
    int cnt = 0;
    for (int base = 0; base < TOK; base += 32) {
        int t = base + lane;
        bool m = (g_eid[t] == warp);
        unsigned bal = __ballot_sync(0xffffffffu, m);
        int pos = cnt + __popc(bal & ((1u << lane) - 1u));
        if (m && pos < CAPN) g_list[warp * CAPN + pos] = t;
        cnt += __popc(bal);
    }
    if (lane == 0) g_cnt[warp] = cnt < CAPN ? cnt : CAPN;
}

// ---------------- MoE GEMM1 (1xTF32, k32, 3-stage) ----------------
__global__ __launch_bounds__(256, 2) void moe1_tc_kernel(const float* __restrict__ wi) {
    int e = blockIdx.z;
    int cnt = g_cnt[e];
    int row0 = blockIdx.y * 128;
    if (row0 >= cnt) return;
    int col0 = blockIdx.x * 128;
    float acc[2][8][4]; ZERO_ACC(acc);
    gemm_tc_1xk32(g_xn, wi + (size_t)e * EE * FF, EE, FF, EE, row0, col0,
                  g_list + e * CAPN, cnt, acc);
    int warp = threadIdx.x >> 5, lane = threadIdx.x & 31;
    int wm = (warp & 3) * 32, wn = (warp >> 2) * 64;
    int g = lane >> 2, tq = lane & 3;
    #pragma unroll
    for (int mt = 0; mt < 2; mt++) {
        #pragma unroll
        for (int p = 0; p < 2; p++) {
            int r = row0 + wm + mt * 16 + g + p * 8;
            if (r < cnt) {
                #pragma unroll
                for (int nt = 0; nt < 8; nt++) {
                    int c = col0 + wn + nt * 8 + tq * 2;
                    float x0 = acc[mt][nt][p * 2], x1 = acc[mt][nt][p * 2 + 1];
                    float g0 = 0.5f * x0 * (1.0f + erff(x0 * 0.70710678118654752f));
                    float g1 = 0.5f * x1 * (1.0f + erff(x1 * 0.70710678118654752f));
                    *(float2*)&g_h[((size_t)e * CAPN + r) * FF + c] =
                        make_float2(tf32_rna(g0), tf32_rna(g1));
                }
            }
        }
    }
}

// ---------------- MoE GEMM2 (1xTF32, k32, 3-stage) ----------------
__global__ __launch_bounds__(256, 2) void moe2_tc_kernel(const float* __restrict__ wo,
                                                         float* __restrict__ out) {
    int e = blockIdx.z;
    int cnt = g_cnt[e];
    int row0 = blockIdx.y * 128;
    if (row0 >= cnt) return;
    int col0 = blockIdx.x * 128;
    float acc[2][8][4]; ZERO_ACC(acc);
    gemm_tc_1xk32(g_h + (size_t)e * CAPN * FF, wo + (size_t)e * FF * EE, FF, EE, FF,
                  row0, col0, nullptr, cnt, acc);
    int warp = threadIdx.x >> 5, lane = threadIdx.x & 31;
    int wm = (warp & 3) * 32, wn = (warp >> 2) * 64;
    int g = lane >> 2, tq = lane & 3;
    #pragma unroll
    for (int mt = 0; mt < 2; mt++) {
        #pragma unroll
        for (int p = 0; p < 2; p++) {
            int r = row0 + wm + mt * 16 + g + p * 8;
            if (r < cnt) {
                int tok = g_list[e * CAPN + r];
                #pragma unroll
                for (int nt = 0; nt < 8; nt++) {
                    int c = col0 + wn + nt * 8 + tq * 2;
                    size_t i0 = (size_t)tok * EE + c;
                    out[i0]     += acc[mt][nt][p * 2];
                    out[i0 + 1] += acc[mt][nt][p * 2 + 1];
                }
            }
        }
    }
}

// ---------------- launch ----------------
extern "C" void kernel_launch(void* const* d_in, const int* in_sizes, int n_in,
                              void* d_out, int out_size) {
    const float* q     = (const float*)d_in[0];
    const float* k     = (const float*)d_in[1];
    const float* v     = (const float*)d_in[2];
    const float* in_w  = (const float*)d_in[3];
    const float* in_b  = (const float*)d_in[4];
    const float* out_w = (const float*)d_in[5];
    const float* out_b = (const float*)d_in[6];
    const float* n1s   = (const float*)d_in[7];
    const float* n1b   = (const float*)d_in[8];
    const float* n2s   = (const float*)d_in[9];
    const float* n2b   = (const float*)d_in[10];
    const float* rw    = (const float*)d_in[11];
    const float* wi    = (const float*)d_in[12];
    const float* wo    = (const float*)d_in[13];
    float* out = (float*)d_out;

    cudaFuncSetAttribute(attn_tc_kernel, cudaFuncAttributeMaxDynamicSharedMemorySize, ATTN_SMEM_BYTES);
    cudaFuncSetAttribute(qkv_tc_kernel, cudaFuncAttributeMaxDynamicSharedMemorySize, SMBIG_BYTES);
    cudaFuncSetAttribute(outproj_tc_kernel, cudaFuncAttributeMaxDynamicSharedMemorySize, SMBIG_BYTES);
    cudaFuncSetAttribute(moe1_tc_kernel, cudaFuncAttributeMaxDynamicSharedMemorySize, SMK32_BYTES);
    cudaFuncSetAttribute(moe2_tc_kernel, cudaFuncAttributeMaxDynamicSharedMemorySize, SMK32_BYTES);

    split_w_kernel<<<(4 * EE * EE) / 256, 256>>>(in_w, out_w);
    ln1_rope_kernel<<<dim3(TOK, 3), 256>>>(q, k, v, n1s, n1b);
    qkv_tc_kernel<<<dim3(EE / 128, TOK / 256, 3), 512, SMBIG_BYTES>>>(in_b);
    attn_tc_kernel<<<dim3(SQ / 128, NB * NH), 256, ATTN_SMEM_BYTES>>>();
    outproj_tc_kernel<<<dim3(EE / 128, TOK / 256), 512, SMBIG_BYTES>>>(out_b, q, out);
    ln2_router_kernel<<<TOK, 256>>>(n2s, n2b, rw);
    capacity_kernel<<<1, 256>>>();
    moe1_tc_kernel<<<dim3(FF / 128, CAPN / 128, NEXP), 256, SMK32_BYTES>>>(wi);
    moe2_tc_kernel<<<dim3(EE / 128, CAPN / 128, NEXP), 256, SMK32_BYTES>>>(wo, out);
}

// round 17
// speedup vs baseline: 1.0849x; 1.0849x over previous
#include <cuda_runtime.h>
#include <math.h>
#include <stdint.h>

#define SQ   2048
#define NB   4
#define EE   1024
#define FF   4096
#define NEXP 8
#define CAPN 2048
#define NH   16
#define HD   64
#define TOK  (SQ*NB)

// ---------------- pre-split global planes ----------------
__device__ float g_qnh[TOK*EE]; __device__ float g_qnl[TOK*EE];
__device__ float g_knh[TOK*EE]; __device__ float g_knl[TOK*EE];
__device__ float g_vnh[TOK*EE]; __device__ float g_vnl[TOK*EE];
__device__ float g_qph[TOK*EE]; __device__ float g_qpl[TOK*EE];
__device__ float g_kph[TOK*EE]; __device__ float g_kpl[TOK*EE];
__device__ float g_vph[TOK*EE]; __device__ float g_vpl[TOK*EE];
__device__ float g_ctxh[TOK*EE]; __device__ float g_ctxl[TOK*EE];
__device__ float g_x[TOK*EE];
__device__ float g_xn[TOK*EE];
__device__ float g_iwh[3*EE*EE]; __device__ float g_iwl[3*EE*EE];
__device__ float g_owh[EE*EE];   __device__ float g_owl[EE*EE];
__device__ float g_h[(size_t)NEXP*CAPN*FF];
__device__ float g_ropeinv[EE/2];
__device__ int   g_eid[TOK];
__device__ int   g_list[NEXP*CAPN];
__device__ int   g_cnt[NEXP];

// ---------------- helpers ----------------
__device__ __forceinline__ float tf32_rna(float x) {
    uint32_t u; asm("cvt.rna.tf32.f32 %0, %1;" : "=r"(u) : "f"(x));
    return __uint_as_float(u);
}
__device__ __forceinline__ void split2(float x, float& h, float& l) {
    h = tf32_rna(x); l = tf32_rna(x - h);
}
__device__ __forceinline__ void mma8(float* d, const float* a, const float* b) {
    asm volatile(
        "mma.sync.aligned.m16n8k8.row.col.f32.tf32.tf32.f32 "
        "{%0,%1,%2,%3}, {%4,%5,%6,%7}, {%8,%9}, {%0,%1,%2,%3};"
        : "+f"(d[0]), "+f"(d[1]), "+f"(d[2]), "+f"(d[3])
        : "r"(__float_as_uint(a[0])), "r"(__float_as_uint(a[1])),
          "r"(__float_as_uint(a[2])), "r"(__float_as_uint(a[3])),
          "r"(__float_as_uint(b[0])), "r"(__float_as_uint(b[1])));
}
__device__ __forceinline__ void cpa16(uint32_t dst, const void* src) {
    asm volatile("cp.async.cg.shared.global [%0], [%1], 16;" :: "r"(dst), "l"(src));
}
__device__ __forceinline__ void cp_commit() { asm volatile("cp.async.commit_group;"); }
template<int N> __device__ __forceinline__ void cp_wait() {
    asm volatile("cp.async.wait_group %0;" :: "n"(N));
}
__device__ __forceinline__ uint32_t s2u(const void* p) {
    uint32_t a;
    asm("{ .reg .u64 t; cvta.to.shared.u64 t, %1; cvt.u32.u64 %0, t; }" : "=r"(a) : "l"(p));
    return a;
}

__device__ __forceinline__ float blk_sum256(float v) {
    __shared__ float red[8];
    #pragma unroll
    for (int o = 16; o > 0; o >>= 1) v += __shfl_xor_sync(0xffffffffu, v, o);
    if ((threadIdx.x & 31) == 0) red[threadIdx.x >> 5] = v;
    __syncthreads();
    float s = 0.f;
    #pragma unroll
    for (int i = 0; i < 8; i++) s += red[i];
    __syncthreads();
    return s;
}

// ---------------- one-shot weight split (+ rope table) ----------------
__global__ void split_w_kernel(const float* __restrict__ inw, const float* __restrict__ outw) {
    int i = blockIdx.x * 256 + threadIdx.x;
    if (i < EE / 2)
        g_ropeinv[i] = (float)(1.0 / pow(10000.0, (double)i * (1.0 / 512.0)));
    const int NIW = 3 * EE * EE;
    float h, l;
    if (i < NIW) {
        split2(inw[i], h, l);
        g_iwh[i] = h; g_iwl[i] = l;
    } else {
        int j = i - NIW;
        split2(outw[j], h, l);
        g_owh[j] = h; g_owl[j] = l;
    }
}

// ---------------- LN1 + RoPE ----------------
__global__ void ln1_rope_kernel(const float* __restrict__ q, const float* __restrict__ k,
                                const float* __restrict__ v,
                                const float* __restrict__ sc, const float* __restrict__ bi) {
    int z = blockIdx.y, t = blockIdx.x;
    const float* x = ((z == 0) ? q : (z == 1) ? k : v) + (size_t)t * EE;
    float* oh = ((z == 0) ? g_qnh : (z == 1) ? g_knh : g_vnh) + (size_t)t * EE;
    float* ol = ((z == 0) ? g_qnl : (z == 1) ? g_knl : g_vnl) + (size_t)t * EE;
    int srow = t / NB;
    float s = 0.f;
    for (int i = threadIdx.x; i < EE; i += 256) s += x[i];
    float mean = blk_sum256(s) * (1.0f / EE);
    float vs = 0.f;
    for (int i = threadIdx.x; i < EE; i += 256) { float d = x[i] - mean; vs += d * d; }
    float rstd = rsqrtf(blk_sum256(vs) * (1.0f / EE) + 1e-5f);
    for (int i = threadIdx.x; i < EE / 2; i += 256) {
        float x1 = (x[i]       - mean) * rstd * sc[i]       + bi[i];
        float x2 = (x[i + 512] - mean) * rstd * sc[i + 512] + bi[i + 512];
        float fr = (float)srow * g_ropeinv[i];
        float sn, cs; sincosf(fr, &sn, &cs);
        float o1 = x1 * cs - x2 * sn;
        float o2 = x1 * sn + x2 * cs;
        float h, l;
        split2(o1, h, l); oh[i] = h;       ol[i] = l;
        split2(o2, h, l); oh[i + 512] = h; ol[i + 512] = l;
    }
}

// ---------------- LN2 + router fused ----------------
__global__ void ln2_router_kernel(const float* __restrict__ sc, const float* __restrict__ bi,
                                  const float* __restrict__ rw) {
    int t = blockIdx.x;
    const float* x = g_x + (size_t)t * EE;
    float* o = g_xn + (size_t)t * EE;
    float s = 0.f;
    for (int i = threadIdx.x; i < EE; i += 256) s += x[i];
    float mean = blk_sum256(s) * (1.0f / EE);
    float vs = 0.f;
    for (int i = threadIdx.x; i < EE; i += 256) { float d = x[i] - mean; vs += d * d; }
    float rstd = rsqrtf(blk_sum256(vs) * (1.0f / EE) + 1e-5f);
    float a[NEXP];
    #pragma unroll
    for (int e = 0; e < NEXP; e++) a[e] = 0.f;
    for (int i = threadIdx.x; i < EE; i += 256) {
        float xn = (x[i] - mean) * rstd * sc[i] + bi[i];
        o[i] = tf32_rna(xn);
        #pragma unroll
        for (int e = 0; e < NEXP; e++) a[e] += xn * rw[i * NEXP + e];
    }
    __shared__ float red[8][NEXP];
    #pragma unroll
    for (int e = 0; e < NEXP; e++) {
        float v = a[e];
        #pragma unroll
        for (int o2 = 16; o2 > 0; o2 >>= 1) v += __shfl_xor_sync(0xffffffffu, v, o2);
        if ((threadIdx.x & 31) == 0) red[threadIdx.x >> 5][e] = v;
    }
    __syncthreads();
    if (threadIdx.x == 0) {
        int best = 0; float bv = -1e30f;
        #pragma unroll
        for (int e = 0; e < NEXP; e++) {
            float sum = 0.f;
            #pragma unroll
            for (int w = 0; w < 8; w++) sum += red[w][e];
            if (sum > bv) { bv = sum; best = e; }
        }
        g_eid[t] = best;
    }
}

// ================= 3xTF32 GEMM, 128x128, swizzled stride-16, 3-stage, 2 CTAs/SM =================
// stage: Ah(128x16) Al Bh(128x16) Bl = 8192 floats = 32KB; 3 stages = 96KB
#define S3_AH 0
#define S3_AL 2048
#define S3_BH 4096
#define S3_BL 6144
#define S3_STAGE 8192
#define SM3_BYTES (3 * S3_STAGE * 4)   // 98304

__device__ __forceinline__ void gemm_tc_v5(
    const float* __restrict__ Ahg, const float* __restrict__ Alg,
    const float* __restrict__ Bhg, const float* __restrict__ Blg,
    int lda, int ldb, int K, int row0, int col0, int valid,
    float acc[2][8][4])
{
    extern __shared__ float smf[];
    const int tid = threadIdx.x;
    const int warp = tid >> 5, lane = tid & 31;
    const int g = lane >> 2, tq = lane & 3;
    const int wm = (warp & 3) * 32, wn = (warp >> 2) * 64;
    const int swz = g >> 1;             // constant swizzle index for ALL fragment reads

    uint32_t smb = s2u(smf);

    // copy setup: 2 iterations, each handles one (row, chunk) slot for A and B
    const float* pAh[2]; const float* pAl[2];
    const float* pBh[2]; const float* pBl[2];
    uint32_t dstA[2], dstB[2];
    #pragma unroll
    for (int i = 0; i < 2; i++) {
        int id = tid + i * 256;
        int r = id >> 2, q4 = id & 3;
        int swr = (r >> 1) & 3;
        int qs = ((q4 ^ swr) << 2);     // swizzled smem column (floats)
        int gr = row0 + r; if (gr >= valid) gr = valid - 1;
        pAh[i] = Ahg + (size_t)gr * lda + q4 * 4;
        pAl[i] = Alg + (size_t)gr * lda + q4 * 4;
        dstA[i] = r * 16 + qs;
        pBh[i] = Bhg + (size_t)(col0 + r) * ldb + q4 * 4;
        pBl[i] = Blg + (size_t)(col0 + r) * ldb + q4 * 4;
        dstB[i] = S3_BH + r * 16 + qs;
    }

    auto docopy = [&](int k0, int st) {
        uint32_t base = smb + (uint32_t)(st * S3_STAGE) * 4u;
        #pragma unroll
        for (int i = 0; i < 2; i++) {
            cpa16(base + dstA[i] * 4, pAh[i] + k0);
            cpa16(base + (dstA[i] + S3_AL) * 4, pAl[i] + k0);
            cpa16(base + dstB[i] * 4, pBh[i] + k0);
            cpa16(base + (dstB[i] + (S3_BL - S3_BH)) * 4, pBl[i] + k0);
        }
    };

    auto mmaT = [&](int st) {
        const float* Ah = smf + st * S3_STAGE + S3_AH;
        const float* Al = smf + st * S3_STAGE + S3_AL;
        const float* Bh = smf + st * S3_STAGE + S3_BH;
        const float* Bl = smf + st * S3_STAGE + S3_BL;
        #pragma unroll
        for (int ks = 0; ks < 2; ks++) {
            int colA = (((2 * ks) ^ swz) << 2) + tq;        // column of kk
            int colB = (((2 * ks + 1) ^ swz) << 2) + tq;    // column of kk+4
            float ah[2][4], al[2][4];
            #pragma unroll
            for (int mt = 0; mt < 2; mt++) {
                int r = wm + mt * 16 + g;
                ah[mt][0] = Ah[r * 16 + colA];       ah[mt][1] = Ah[(r + 8) * 16 + colA];
                ah[mt][2] = Ah[r * 16 + colB];       ah[mt][3] = Ah[(r + 8) * 16 + colB];
                al[mt][0] = Al[r * 16 + colA];       al[mt][1] = Al[(r + 8) * 16 + colA];
                al[mt][2] = Al[r * 16 + colB];       al[mt][3] = Al[(r + 8) * 16 + colB];
            }
            #pragma unroll
            for (int nt = 0; nt < 8; nt++) {
                int n = wn + nt * 8 + g;
                float bh[2] = { Bh[n * 16 + colA], Bh[n * 16 + colB] };
                float bl[2] = { Bl[n * 16 + colA], Bl[n * 16 + colB] };
                #pragma unroll
                for (int mt = 0; mt < 2; mt++) {
                    mma8(acc[mt][nt], ah[mt], bl);
                    mma8(acc[mt][nt], al[mt], bh);
                    mma8(acc[mt][nt], ah[mt], bh);
                }
            }
        }
    };

    const int T = K >> 4;
    docopy(0, 0); cp_commit();
    docopy(16, 1); cp_commit();
    int s0 = 0;
    for (int t = 0; t < T; t++) {
        if (t + 1 < T) cp_wait<1>(); else cp_wait<0>();
        __syncthreads();
        if (t + 2 < T) {
            int s2 = s0 + 2; if (s2 >= 3) s2 -= 3;
            docopy((t + 2) * 16, s2);
            cp_commit();
        }
        mmaT(s0);
        if (++s0 == 3) s0 = 0;
    }
    __syncthreads();
}

// ================= 1xTF32 GEMM, k-tile 32, 3-stage pipeline (MoE) =================
#define KA_STR 36
#define K32_STAGE (128 * KA_STR + 32 * 132)
#define SMK32_BYTES (3 * K32_STAGE * 4)

__device__ __forceinline__ void gemm_tc_1xk32(
    const float* __restrict__ Ag, const float* __restrict__ Bg,
    int lda, int ldb, int K, int row0, int col0,
    const int* __restrict__ gather, int valid,
    float acc[2][8][4])
{
    extern __shared__ float smf[];
    const int tid = threadIdx.x;
    const int warp = tid >> 5, lane = tid & 31;
    const int g = lane >> 2, tq = lane & 3;
    const int wm = (warp & 3) * 32, wn = (warp >> 2) * 64;

    uint32_t smb = s2u(smf);

    const float* pA[4]; const float* pB[4];
    uint32_t dA[4], dB[4];
    #pragma unroll
    for (int i = 0; i < 4; i++) {
        int id = tid + i * 256;
        int r = id >> 3, q = (id & 7) * 4;
        int gr = row0 + r; if (gr >= valid) gr = valid - 1;
        int ar = gather ? gather[gr] : gr;
        pA[i] = Ag + (size_t)ar * lda + q;
        dA[i] = r * KA_STR + q;
        int kr = id >> 5, n4 = (id & 31) * 4;
        pB[i] = Bg + (size_t)kr * ldb + col0 + n4;
        dB[i] = 128 * KA_STR + kr * 132 + n4;
    }

    auto docopy = [&](int k0, int st) {
        uint32_t base = smb + (uint32_t)(st * K32_STAGE) * 4u;
        #pragma unroll
        for (int i = 0; i < 4; i++) cpa16(base + dA[i] * 4, pA[i] + k0);
        #pragma unroll
        for (int i = 0; i < 4; i++) cpa16(base + dB[i] * 4, pB[i] + (size_t)k0 * ldb);
    };

    auto mmaT = [&](int st) {
        const float* As = smf + st * K32_STAGE;
        const float* Bs = As + 128 * KA_STR;
        #pragma unroll
        for (int ks = 0; ks < 4; ks++) {
            int kk = ks * 8 + tq;
            float ah[2][4];
            #pragma unroll
            for (int mt = 0; mt < 2; mt++) {
                int r = wm + mt * 16 + g;
                ah[mt][0] = As[r * KA_STR + kk];     ah[mt][1] = As[(r + 8) * KA_STR + kk];
                ah[mt][2] = As[r * KA_STR + kk + 4]; ah[mt][3] = As[(r + 8) * KA_STR + kk + 4];
            }
            #pragma unroll
            for (int nt = 0; nt < 8; nt++) {
                int n = wn + nt * 8 + g;
                float bh[2] = { Bs[kk * 132 + n], Bs[(kk + 4) * 132 + n] };
                #pragma unroll
                for (int mt = 0; mt < 2; mt++)
                    mma8(acc[mt][nt], ah[mt], bh);
            }
        }
    };

    const int T = K >> 5;
    docopy(0, 0); cp_commit();
    docopy(32, 1); cp_commit();
    int s0 = 0;
    for (int t = 0; t < T; t++) {
        if (t + 1 < T) cp_wait<1>(); else cp_wait<0>();
        __syncthreads();
        if (t + 2 < T) {
            int s2 = s0 + 2; if (s2 >= 3) s2 -= 3;
            docopy((t + 2) * 32, s2);
            cp_commit();
        }
        mmaT(s0);
        if (++s0 == 3) s0 = 0;
    }
    __syncthreads();
}

#define ZERO_ACC(acc) { \
    _Pragma("unroll") for (int a_ = 0; a_ < 2; a_++) \
    _Pragma("unroll") for (int b_ = 0; b_ < 8; b_++) \
    _Pragma("unroll") for (int c_ = 0; c_ < 4; c_++) acc[a_][b_][c_] = 0.f; }

// ---------------- QKV projection (3xTF32); permuted epilogue layouts ----------------
__global__ __launch_bounds__(256, 2) void qkv_tc_kernel(const float* __restrict__ bias) {
    int z = blockIdx.z;
    const float* Ah = (z == 0) ? g_qnh : (z == 1) ? g_knh : g_vnh;
    const float* Al = (z == 0) ? g_qnl : (z == 1) ? g_knl : g_vnl;
    float* Ch = (z == 0) ? g_qph : (z == 1) ? g_kph : g_vph;
    float* Cl = (z == 0) ? g_qpl : (z == 1) ? g_kpl : g_vpl;
    int row0 = blockIdx.y * 128, col0 = blockIdx.x * 128;
    float acc[2][8][4]; ZERO_ACC(acc);
    gemm_tc_v5(Ah, Al, g_iwh + (size_t)z * EE * EE, g_iwl + (size_t)z * EE * EE,
               EE, EE, EE, row0, col0, TOK, acc);
    int warp = threadIdx.x >> 5, lane = threadIdx.x & 31;
    int wm = (warp & 3) * 32, wn = (warp >> 2) * 64;
    int g = lane >> 2, tq = lane & 3;
    float scale = (z == 0) ? 0.125f : 1.0f;
    int pi0 = ((tq & 1) << 2) | (tq >> 1);
    #pragma unroll
    for (int mt = 0; mt < 2; mt++) {
        #pragma unroll
        for (int p = 0; p < 2; p++) {
            int r = row0 + wm + mt * 16 + g + p * 8;
            #pragma unroll
            for (int nt = 0; nt < 8; nt++) {
                int c = col0 + wn + nt * 8 + tq * 2;
                float v0 = (acc[mt][nt][p * 2]     + bias[z * EE + c])     * scale;
                float v1 = (acc[mt][nt][p * 2 + 1] + bias[z * EE + c + 1]) * scale;
                float h0, l0, h1, l1;
                split2(v0, h0, l0); split2(v1, h1, l1);
                if (z < 2) {
                    size_t base = (size_t)r * EE + (c & ~7);
                    Ch[base + pi0]     = h0;  Ch[base + pi0 + 2] = h1;
                    Cl[base + pi0]     = l0;  Cl[base + pi0 + 2] = l1;
                } else {
                    int kt = r >> 2, bb = r & 3;
                    size_t vb = (((size_t)(kt >> 1) * NB + bb) * EE + c) * 2 + (kt & 1);
                    Ch[vb]     = h0;  Ch[vb + 2] = h1;
                    Cl[vb]     = l0;  Cl[vb + 2] = l1;
                }
            }
        }
    }
}

// ---------------- out projection (3xTF32) + bias + residual ----------------
__global__ __launch_bounds__(256, 2) void outproj_tc_kernel(const float* __restrict__ bias,
                                                            const float* __restrict__ resid,
                                                            float* __restrict__ out) {
    int row0 = blockIdx.y * 128, col0 = blockIdx.x * 128;
    float acc[2][8][4]; ZERO_ACC(acc);
    gemm_tc_v5(g_ctxh, g_ctxl, g_owh, g_owl, EE, EE, EE, row0, col0, TOK, acc);
    int warp = threadIdx.x >> 5, lane = threadIdx.x & 31;
    int wm = (warp & 3) * 32, wn = (warp >> 2) * 64;
    int g = lane >> 2, tq = lane & 3;
    #pragma unroll
    for (int mt = 0; mt < 2; mt++) {
        #pragma unroll
        for (int p = 0; p < 2; p++) {
            int r = row0 + wm + mt * 16 + g + p * 8;
            #pragma unroll
            for (int nt = 0; nt < 8; nt++) {
                int c = col0 + wn + nt * 8 + tq * 2;
                size_t o = (size_t)r * EE + c;
                float v0 = acc[mt][nt][p * 2]     + bias[c]     + resid[o];
                float v1 = acc[mt][nt][p * 2 + 1] + bias[c + 1] + resid[o + 1];
                g_x[o] = v0; g_x[o + 1] = v1;
                out[o] = v0; out[o + 1] = v1;
            }
        }
    }
}

// ================= flash attention (R15: no-max softmax, single-barrier) =================
#define QS  76
#define KSS 72
#define VPS 136
#define QH_O 0
#define QL_O (128*QS)
#define KH_O (2*128*QS)
#define KL_O (KH_O + 2*64*KSS)
#define VH_O (KL_O + 2*64*KSS)
#define VL_O (VH_O + 2*32*VPS)
#define ATTN_SMEM_BYTES ((VL_O + 2*32*VPS) * 4)

__global__ __launch_bounds__(256, 1) void attn_tc_kernel() {
    extern __shared__ float sm[];
    uint32_t smb = s2u(sm);

    int bh = blockIdx.y;
    int b = bh >> 4, h = bh & 15;
    int q0 = blockIdx.x * 128;
    int tid = threadIdx.x, warp = tid >> 5, lane = tid & 31;
    int g = lane >> 2, tq = lane & 3;
    int qw = warp * 16;

    const int row = tid >> 2, ch = (tid & 3) * 16;
    const int vp = tid >> 3, vch = (tid & 7) * 16;

    {
        size_t s0 = ((size_t)(q0 + row) * NB + b) * EE + h * HD + ch;
        size_t s1 = ((size_t)(q0 + row + 64) * NB + b) * EE + h * HD + ch;
        #pragma unroll
        for (int j = 0; j < 4; j++) {
            int c4 = ch + j * 4;
            cpa16(smb + (QH_O + row * QS + c4) * 4,        g_qph + s0 + j * 4);
            cpa16(smb + (QL_O + row * QS + c4) * 4,        g_qpl + s0 + j * 4);
            cpa16(smb + (QH_O + (row + 64) * QS + c4) * 4, g_qph + s1 + j * 4);
            cpa16(smb + (QL_O + (row + 64) * QS + c4) * 4, g_qpl + s1 + j * 4);
        }
    }

    auto docopy = [&](int n0, int st) {
        size_t ksrc = ((size_t)(n0 + row) * NB + b) * EE + h * HD + ch;
        uint32_t kd = (uint32_t)(KH_O + st * 64 * KSS + row * KSS + ch);
        #pragma unroll
        for (int j = 0; j < 4; j++) {
            uint32_t f = j * 4;
            cpa16(smb + (kd + f) * 4,                 g_kph + ksrc + f);
            cpa16(smb + (kd + (KL_O - KH_O) + f) * 4, g_kpl + ksrc + f);
        }
        size_t vsrc = (((size_t)((n0 >> 1) + vp) * NB + b) * EE + h * HD) * 2 + vch;
        uint32_t vd = (uint32_t)(VH_O + st * 32 * VPS + vp * VPS + vch);
        #pragma unroll
        for (int j = 0; j < 4; j++) {
            uint32_t f = j * 4;
            cpa16(smb + (vd + f) * 4,                 g_vph + vsrc + f);
            cpa16(smb + (vd + (VL_O - VH_O) + f) * 4, g_vpl + vsrc + f);
        }
    };

    docopy(0, 0); cp_commit();
    cp_wait<0>(); __syncthreads();

    float qh[8][4], ql[8][4];
    {
        const float* Qh = sm + QH_O;
        const float* Ql = sm + QL_O;
        int r = qw + g;
        #pragma unroll
        for (int ks = 0; ks < 8; ks++) {
            int off = ks * 8 + tq * 2;
            float2 a0 = *(const float2*)&Qh[r * QS + off];
            float2 a1 = *(const float2*)&Qh[(r + 8) * QS + off];
            qh[ks][0] = a0.x; qh[ks][1] = a1.x; qh[ks][2] = a0.y; qh[ks][3] = a1.y;
            float2 b0 = *(const float2*)&Ql[r * QS + off];
            float2 b1 = *(const float2*)&Ql[(r + 8) * QS + off];
            ql[ks][0] = b0.x; ql[ks][1] = b1.x; ql[ks][2] = b0.y; ql[ks][3] = b1.y;
        }
    }

    float o[8][4];
    #pragma unroll
    for (int nt = 0; nt < 8; nt++)
        #pragma unroll
        for (int j = 0; j < 4; j++) o[nt][j] = 0.f;
    float lsum0 = 0.f, lsum1 = 0.f;

    int st = 0;
    for (int n0 = 0; n0 < SQ; n0 += 64) {
        if (n0 + 64 < SQ) { docopy(n0 + 64, st ^ 1); cp_commit(); }

        const float* Kh = sm + KH_O + st * 64 * KSS;
        const float* Kl = sm + KL_O + st * 64 * KSS;
        const float* Vh = sm + VH_O + st * 32 * VPS;
        const float* Vl = sm + VL_O + st * 32 * VPS;

        float s[8][4];
        #pragma unroll
        for (int nt = 0; nt < 8; nt++)
            #pragma unroll
            for (int j = 0; j < 4; j++) s[nt][j] = 0.f;
        #pragma unroll
        for (int ks = 0; ks < 8; ks++) {
            int off = ks * 8 + tq * 2;
            #pragma unroll
            for (int nt = 0; nt < 8; nt++) {
                int n = nt * 8 + g;
                float2 bh2 = *(const float2*)&Kh[n * KSS + off];
                float2 bl2 = *(const float2*)&Kl[n * KSS + off];
                float bhv[2] = { bh2.x, bh2.y };
                float blv[2] = { bl2.x, bl2.y };
                mma8(s[nt], qh[ks], blv);
                mma8(s[nt], ql[ks], bhv);
                mma8(s[nt], qh[ks], bhv);
            }
        }

        #pragma unroll
        for (int nt = 0; nt < 8; nt++) {
            s[nt][0] = __expf(s[nt][0]); lsum0 += s[nt][0];
            s[nt][1] = __expf(s[nt][1]); lsum0 += s[nt][1];
            s[nt][2] = __expf(s[nt][2]); lsum1 += s[nt][2];
            s[nt][3] = __expf(s[nt][3]); lsum1 += s[nt][3];
        }

        #pragma unroll
        for (int ks = 0; ks < 8; ks++) {
            float ah[4], al[4];
            split2(s[ks][0], ah[0], al[0]);
            split2(s[ks][2], ah[1], al[1]);
            split2(s[ks][1], ah[2], al[2]);
            split2(s[ks][3], ah[3], al[3]);
            int vrow = ks * 4 + tq;
            #pragma unroll
            for (int nt = 0; nt < 8; nt++) {
                int n = nt * 8 + g;
                float2 bh2 = *(const float2*)&Vh[vrow * VPS + n * 2];
                float2 bl2 = *(const float2*)&Vl[vrow * VPS + n * 2];
                float bhv[2] = { bh2.x, bh2.y };
                float blv[2] = { bl2.x, bl2.y };
                mma8(o[nt], ah, blv);
                mma8(o[nt], al, bhv);
                mma8(o[nt], ah, bhv);
            }
        }

        cp_wait<0>(); __syncthreads();
        st ^= 1;
    }

    lsum0 += __shfl_xor_sync(0xffffffffu, lsum0, 1);
    lsum0 += __shfl_xor_sync(0xffffffffu, lsum0, 2);
    lsum1 += __shfl_xor_sync(0xffffffffu, lsum1, 1);
    lsum1 += __shfl_xor_sync(0xffffffffu, lsum1, 2);
    float inv0 = 1.0f / lsum0, inv1 = 1.0f / lsum1;

    int r0 = q0 + qw + g, r1 = r0 + 8;
    #pragma unroll
    for (int nt = 0; nt < 8; nt++) {
        int d = nt * 8 + tq * 2;
        size_t o0 = ((size_t)r0 * NB + b) * EE + h * HD + d;
        size_t o1 = ((size_t)r1 * NB + b) * EE + h * HD + d;
        float h0, l0v, h1, l1v;
        split2(o[nt][0] * inv0, h0, l0v); split2(o[nt][1] * inv0, h1, l1v);
        *(float2*)&g_ctxh[o0] = make_float2(h0, h1);
        *(float2*)&g_ctxl[o0] = make_float2(l0v, l1v);
        split2(o[nt][2] * inv1, h0, l0v); split2(o[nt][3] * inv1, h1, l1v);
        *(float2*)&g_ctxh[o1] = make_float2(h0, h1);
        *(float2*)&g_ctxl[o1] = make_float2(l0v, l1v);
    }
}

// ---------------- capacity: warp-ballot scan ----------------
__global__ void capacity_kernel() {
    int warp = threadIdx.x >> 5, lane = threadIdx.x & 31;
    if (warp >= NEXP) return;
    int cnt = 0;
    for (int base = 0; base < TOK; base += 32) {
        int t = base + lane;
        bool m = (g_eid[t] == warp);
        unsigned bal = __ballot_sync(0xffffffffu, m);
        int pos = cnt + __popc(bal & ((1u << lane) - 1u));
        if (m && pos < CAPN) g_list[warp * CAPN + pos] = t;
        cnt += __popc(bal);
    }
    if (lane == 0) g_cnt[warp] = cnt < CAPN ? cnt : CAPN;
}

// ---------------- MoE GEMM1 (1xTF32, k32, 3-stage) ----------------
__global__ __launch_bounds__(256, 2) void moe1_tc_kernel(const float* __restrict__ wi) {
    int e = blockIdx.z;
    int cnt = g_cnt[e];
    int row0 = blockIdx.y * 128;
    if (row0 >= cnt) return;
    int col0 = blockIdx.x * 128;
    float acc[2][8][4]; ZERO_ACC(acc);
    gemm_tc_1xk32(g_xn, wi + (size_t)e * EE * FF, EE, FF, EE, row0, col0,
                  g_list + e * CAPN, cnt, acc);
    int warp = threadIdx.x >> 5, lane = threadIdx.x & 31;
    int wm = (warp & 3) * 32, wn = (warp >> 2) * 64;
    int g = lane >> 2, tq = lane & 3;
    #pragma unroll
    for (int mt = 0; mt < 2; mt++) {
        #pragma unroll
        for (int p = 0; p < 2; p++) {
            int r = row0 + wm + mt * 16 + g + p * 8;
            if (r < cnt) {
                #pragma unroll
                for (int nt = 0; nt < 8; nt++) {
                    int c = col0 + wn + nt * 8 + tq * 2;
                    float x0 = acc[mt][nt][p * 2], x1 = acc[mt][nt][p * 2 + 1];
                    float g0 = 0.5f * x0 * (1.0f + erff(x0 * 0.70710678118654752f));
                    float g1 = 0.5f * x1 * (1.0f + erff(x1 * 0.70710678118654752f));
                    *(float2*)&g_h[((size_t)e * CAPN + r) * FF + c] =
                        make_float2(tf32_rna(g0), tf32_rna(g1));
                }
            }
        }
    }
}

// ---------------- MoE GEMM2 (1xTF32, k32, 3-stage) ----------------
__global__ __launch_bounds__(256, 2) void moe2_tc_kernel(const float* __restrict__ wo,
                                                         float* __restrict__ out) {
    int e = blockIdx.z;
    int cnt = g_cnt[e];
    int row0 = blockIdx.y * 128;
    if (row0 >= cnt) return;
    int col0 = blockIdx.x * 128;
    float acc[2][8][4]; ZERO_ACC(acc);
    gemm_tc_1xk32(g_h + (size_t)e * CAPN * FF, wo + (size_t)e * FF * EE, FF, EE, FF,
                  row0, col0, nullptr, cnt, acc);
    int warp = threadIdx.x >> 5, lane = threadIdx.x & 31;
    int wm = (warp & 3) * 32, wn = (warp >> 2) * 64;
    int g = lane >> 2, tq = lane & 3;
    #pragma unroll
    for (int mt = 0; mt < 2; mt++) {
        #pragma unroll
        for (int p = 0; p < 2; p++) {
            int r = row0 + wm + mt * 16 + g + p * 8;
            if (r < cnt) {
                int tok = g_list[e * CAPN + r];
                #pragma unroll
                for (int nt = 0; nt < 8; nt++) {
                    int c = col0 + wn + nt * 8 + tq * 2;
                    size_t i0 = (size_t)tok * EE + c;
                    out[i0]     += acc[mt][nt][p * 2];
                    out[i0 + 1] += acc[mt][nt][p * 2 + 1];
                }
            }
        }
    }
}

// ---------------- launch ----------------
extern "C" void kernel_launch(void* const* d_in, const int* in_sizes, int n_in,
                              void* d_out, int out_size) {
    const float* q     = (const float*)d_in[0];
    const float* k     = (const float*)d_in[1];
    const float* v     = (const float*)d_in[2];
    const float* in_w  = (const float*)d_in[3];
    const float* in_b  = (const float*)d_in[4];
    const float* out_w = (const float*)d_in[5];
    const float* out_b = (const float*)d_in[6];
    const float* n1s   = (const float*)d_in[7];
    const float* n1b   = (const float*)d_in[8];
    const float* n2s   = (const float*)d_in[9];
    const float* n2b   = (const float*)d_in[10];
    const float* rw    = (const float*)d_in[11];
    const float* wi    = (const float*)d_in[12];
    const float* wo    = (const float*)d_in[13];
    float* out = (float*)d_out;

    cudaFuncSetAttribute(attn_tc_kernel, cudaFuncAttributeMaxDynamicSharedMemorySize, ATTN_SMEM_BYTES);
    cudaFuncSetAttribute(qkv_tc_kernel, cudaFuncAttributeMaxDynamicSharedMemorySize, SM3_BYTES);
    cudaFuncSetAttribute(outproj_tc_kernel, cudaFuncAttributeMaxDynamicSharedMemorySize, SM3_BYTES);
    cudaFuncSetAttribute(moe1_tc_kernel, cudaFuncAttributeMaxDynamicSharedMemorySize, SMK32_BYTES);
    cudaFuncSetAttribute(moe2_tc_kernel, cudaFuncAttributeMaxDynamicSharedMemorySize, SMK32_BYTES);

    split_w_kernel<<<(4 * EE * EE) / 256, 256>>>(in_w, out_w);
    ln1_rope_kernel<<<dim3(TOK, 3), 256>>>(q, k, v, n1s, n1b);
    qkv_tc_kernel<<<dim3(EE / 128, TOK / 128, 3), 256, SM3_BYTES>>>(in_b);
    attn_tc_kernel<<<dim3(SQ / 128, NB * NH), 256, ATTN_SMEM_BYTES>>>();
    outproj_tc_kernel<<<dim3(EE / 128, TOK / 128), 256, SM3_BYTES>>>(out_b, q, out);
    ln2_router_kernel<<<TOK, 256>>>(n2s, n2b, rw);
    capacity_kernel<<<1, 256>>>();
    moe1_tc_kernel<<<dim3(FF / 128, CAPN / 128, NEXP), 256, SMK32_BYTES>>>(wi);
    moe2_tc_kernel<<<dim3(EE / 128, CAPN / 128, NEXP), 256, SMK32_BYTES>>>(wo, out);
}